// round 1
// baseline (speedup 1.0000x reference)
#include <cuda_runtime.h>

#define PI_F 3.14159265358979323846f

constexpr int HW      = 81;
constexpr int NG      = 4;
constexpr long long NX = 512LL * 512LL * 81LL;   // 21,233,664 elements of x
constexpr int N4      = (int)(NX / 4);            // 5,308,416 float4 chunks
constexpr int THREADS = 256;
constexpr int BLOCKS  = 1296;                     // 81 * 16 -> stride divisible by 81
constexpr int TOTAL_T = BLOCKS * THREADS;         // 331,776
constexpr int ITERS   = N4 / TOTAL_T;             // 16 exactly

__global__ __launch_bounds__(THREADS)
void gabor_mul_kernel(const float* __restrict__ x,
                      const float* __restrict__ theta,
                      const float* __restrict__ lam,
                      float* __restrict__ out)
{
    // --- Build the 4x81 Gabor filter table in shared memory (tiny) ---
    __shared__ float filt[NG * HW];
    for (int i = threadIdx.x; i < NG * HW; i += THREADS) {
        int g  = i / HW;
        int hw = i % HW;
        float fy = (float)(hw / 9) - 4.0f;   // ys = arange(9) - 4
        float fx = (float)(hw % 9) - 4.0f;   // xs = arange(9) - 4
        float th = theta[g];
        float l  = lam[g];
        float s, c;
        sincosf(th, &s, &c);
        float xr = fx * c + fy * s;
        float yr = -fx * s + fy * c;
        float env = expf(-(xr * xr + yr * yr) * (0.5f / (PI_F * PI_F))); // sigma = pi
        filt[i] = env * cosf(2.0f * PI_F * xr * l);
    }
    __syncthreads();

    // --- Hoist this thread's 16 filter values into registers ---
    // Per-iteration stride TOTAL_T*4 elements is divisible by 81, so the
    // hw phase of each lane is loop-invariant.
    int t0  = blockIdx.x * THREADS + threadIdx.x;
    int hw0 = (int)(((long long)t0 * 4) % HW);

    float f[NG][4];
#pragma unroll
    for (int g = 0; g < NG; g++) {
        int h = hw0;
#pragma unroll
        for (int k = 0; k < 4; k++) {
            f[g][k] = filt[g * HW + h];
            h++;
            if (h == HW) h = 0;
        }
    }

    const float4* __restrict__ x4 = (const float4*)x;

#pragma unroll 4
    for (int it = 0; it < ITERS; it++) {
        int idx = t0 + it * TOTAL_T;
        float4 v = __ldcs(&x4[idx]);
#pragma unroll
        for (int g = 0; g < NG; g++) {
            float4 o;
            o.x = f[g][0] * v.x;
            o.y = f[g][1] * v.y;
            o.z = f[g][2] * v.z;
            o.w = f[g][3] * v.w;
            __stcs(((float4*)(out + (size_t)g * NX)) + idx, o);
        }
    }
}

extern "C" void kernel_launch(void* const* d_in, const int* in_sizes, int n_in,
                              void* d_out, int out_size)
{
    const float* x     = (const float*)d_in[0];
    const float* theta = (const float*)d_in[1];
    const float* lam   = (const float*)d_in[2];
    float* out         = (float*)d_out;

    gabor_mul_kernel<<<BLOCKS, THREADS>>>(x, theta, lam, out);
}